// round 15
// baseline (speedup 1.0000x reference)
#include <cuda_runtime.h>
#include <cstdint>

// ---------------------------------------------------------------------------
// SpGraphAttentionLayer (GAT forward).  N=50000, D=128, O=128, R=64, E=1e6.
//
// Factored form:
//   u = a2 @ a (320); c = u[256:320]
//   xs = x @ a_src^T ; xd = x @ a_dst^T          (prep, per node)
//   sdot_s[n] = x[n]·u[0:128] ; sdot_d[n] = x[n]·u[128:256]   (folded in prep)
//   score[e]  = emb[e]·c + sdot_s[src] + sdot_d[dst]
//   ee[e]     = exp(-leaky(score))
//   rs[n] = Σ ee ; w[n] = Σ ee·emb[e] ; ydot[n] = Σ ee·xd[dst]
//   out[n] = rs>0 ? elu( xs[n] + (ydot[n] + w[n]@a_rel^T)/rs ) : 0
//
// Pipeline:
//   zero/hist/scan : CSR offsets
//   prep           : xs,xd + sdot  (launch #4 -> profiled)
//   passA          : stream emb once -> ee + w-scatter (red.v4) + CSR scatter
//   node           : gather xd[dst] -> ydot, rs  (MLP=16, zero FP atomics)
//   final          : K=64 GEMM (w@a_rel^T) + xs + ydot/rs + elu
// ---------------------------------------------------------------------------

#define NMAX 50000
#define EMAX 1100000
#define GAT_ALPHA 0.2f

__device__ float g_xsd[(size_t)NMAX * 256];   // [n][0:128]=xs, [n][128:256]=xd
__device__ float g_sdot[(size_t)NMAX * 2];
__device__ float g_u[320];
__device__ float g_rowsum[NMAX];
__device__ float g_w[(size_t)NMAX * 64];
__device__ float g_ydot[(size_t)NMAX * 128];
__device__ float g_aT[320 * 128];             // a transposed: [k][o]
__device__ int       g_cnt[NMAX];
__device__ int       g_off[NMAX + 1];
__device__ int       g_cur[NMAX];
__device__ long long g_adj[EMAX];             // (bits(ee)<<32) | dst

__device__ __forceinline__ void fma2(unsigned long long &acc,
                                     unsigned long long a, unsigned long long b) {
    asm("fma.rn.f32x2 %0, %1, %2, %0;" : "+l"(acc) : "l"(a), "l"(b));
}
__device__ __forceinline__ float2 unpack2(unsigned long long v) {
    float2 r;
    asm("mov.b64 {%0, %1}, %2;" : "=f"(r.x), "=f"(r.y) : "l"(v));
    return r;
}

// ---------------------------------------------------------------------------
__global__ void vec_kernel(const float* __restrict__ a, const float* __restrict__ a2) {
    __shared__ float a2s[128];
    int t = threadIdx.x;
    if (t < 128) a2s[t] = a2[t];
    __syncthreads();
    if (t < 320) {
        float acc = 0.f;
        #pragma unroll 8
        for (int o = 0; o < 128; o++) acc += a2s[o] * a[o * 320 + t];
        g_u[t] = acc;
    }
}

// ---------------------------------------------------------------------------
// zero: g_cnt + g_w (w is scatter-accumulated every launch)
// ---------------------------------------------------------------------------
__global__ void zero_kernel(int N) {
    int stride = gridDim.x * blockDim.x;
    int i = blockIdx.x * blockDim.x + threadIdx.x;
    int nw = N * 16;
    float4 z = make_float4(0.f, 0.f, 0.f, 0.f);
    for (int j = i; j < nw; j += stride) ((float4*)g_w)[j] = z;
    for (int j = i; j < N; j += stride) g_cnt[j] = 0;
}

__global__ void hist_kernel(const int* __restrict__ e1, const int* __restrict__ e2,
                            int E1, int E2) {
    int E = E1 + E2;
    int stride = gridDim.x * blockDim.x;
    for (int e = blockIdx.x * blockDim.x + threadIdx.x; e < E; e += stride) {
        int s = (e < E1) ? e1[e] : e2[e - E1];
        atomicAdd(&g_cnt[s], 1);
    }
}

// ---------------------------------------------------------------------------
// prep: xs/xd per-node GEMM + sdot fold. 16 nodes/block, 256 threads.
// (launch #4 -> this gets the ncu capture)
// ---------------------------------------------------------------------------
__global__ void __launch_bounds__(256) prep_kernel(const float* __restrict__ x,
                                                   const float* __restrict__ a, int N) {
    __shared__ float xs_sm[16 * 128];
    __shared__ float us_sm[256];
    int t = threadIdx.x;
    int n0 = blockIdx.x * 16;

    us_sm[t] = g_u[t];

    const float4* xg = (const float4*)(x + (size_t)n0 * 128);
    size_t lim4 = (size_t)N * 32;
    float4 z4 = make_float4(0.f, 0.f, 0.f, 0.f);
    ((float4*)xs_sm)[t]       = ((size_t)n0 * 32 + t       < lim4) ? xg[t]       : z4;
    ((float4*)xs_sm)[t + 256] = ((size_t)n0 * 32 + t + 256 < lim4) ? xg[t + 256] : z4;
    __syncthreads();

    const float* arow = (t < 128) ? (a + (size_t)t * 320)
                                  : (a + (size_t)(t - 128) * 320 + 128);
    unsigned long long acc[16];
    #pragma unroll
    for (int n = 0; n < 16; n++) acc[n] = 0ull;

    #pragma unroll 4
    for (int k4 = 0; k4 < 32; k4++) {
        ulonglong2 wv = ((const ulonglong2*)arow)[k4];
        #pragma unroll
        for (int n = 0; n < 16; n++) {
            ulonglong2 xv = ((const ulonglong2*)(xs_sm + n * 128))[k4];
            fma2(acc[n], xv.x, wv.x);
            fma2(acc[n], xv.y, wv.y);
        }
    }
    #pragma unroll
    for (int n = 0; n < 16; n++) {
        if (n0 + n < N) {
            float2 f = unpack2(acc[n]);
            g_xsd[(size_t)(n0 + n) * 256 + t] = f.x + f.y;
        }
    }

    // sdot fold: node n = t>>4, k-chunk kq = t&15
    int n = t >> 4, kq = t & 15;
    float ps = 0.f, pd = 0.f;
    #pragma unroll
    for (int j = 0; j < 8; j++) {
        float xv = xs_sm[n * 128 + kq * 8 + j];
        ps += xv * us_sm[kq * 8 + j];
        pd += xv * us_sm[128 + kq * 8 + j];
    }
    #pragma unroll
    for (int off = 8; off; off >>= 1) {
        ps += __shfl_xor_sync(0xffffffffu, ps, off);
        pd += __shfl_xor_sync(0xffffffffu, pd, off);
    }
    if (kq == 0 && n0 + n < N) {
        g_sdot[2 * (n0 + n)] = ps;
        g_sdot[2 * (n0 + n) + 1] = pd;
    }
}

// ---------------------------------------------------------------------------
__global__ void __launch_bounds__(1024) scan_kernel(int N) {
    __shared__ int sums[1024];
    int t = threadIdx.x;
    int CH = (N + 1023) >> 10;
    int lo = t * CH;
    int hi = lo + CH; if (hi > N) hi = N; if (lo > N) lo = N;

    int s = 0;
    for (int i = lo; i < hi; i++) s += g_cnt[i];
    sums[t] = s;
    __syncthreads();

    for (int off = 1; off < 1024; off <<= 1) {
        int v = (t >= off) ? sums[t - off] : 0;
        __syncthreads();
        sums[t] += v;
        __syncthreads();
    }

    int run = (t > 0) ? sums[t - 1] : 0;
    for (int i = lo; i < hi; i++) {
        int c = g_cnt[i];
        g_off[i] = run;
        g_cur[i] = run;
        run += c;
    }
    if (t == 1023) g_off[N] = run;
}

// ---------------------------------------------------------------------------
// passA: stream emb once. Warp owns 16 edges/chunk; half-warp h handles
// edges 2i+h in phase i. Outputs: w[src] += ee*emb (red.v4, register-resident
// emb), CSR scatter of (ee,dst) (fused - no g_ee round-trip).
// ---------------------------------------------------------------------------
__global__ void __launch_bounds__(256) passA_kernel(
    const int* __restrict__ edge1, const float* __restrict__ emb1,
    const int* __restrict__ edge2, const float* __restrict__ emb2,
    int E1i, int E2i)
{
    const long long E1 = E1i, E2 = E2i;
    const long long E = E1 + E2;
    const long long CH = (E + 15) >> 4;

    const int lane = threadIdx.x & 31;
    const int sub  = lane & 15;
    const int half = lane >> 4;

    long long gwarp = (long long)blockIdx.x * (blockDim.x >> 5) + (threadIdx.x >> 5);
    const long long nwarps = (long long)gridDim.x * (blockDim.x >> 5);

    const float4 c4 = *(const float4*)(g_u + 256 + sub * 4);

    for (long long ch = gwarp; ch < CH; ch += nwarps) {
        const long long base = ch << 4;

        long long ge = base + sub;
        long long gec = (ge < E) ? ge : (E - 1);
        int s, d;
        if (gec < E1) { s = edge1[gec]; d = edge1[E1 + gec]; }
        else { long long g2 = gec - E1; s = edge2[g2]; d = edge2[E2 + g2]; }
        float ssd = g_sdot[2 * s] + g_sdot[2 * d + 1];

        float4 em[8];
        float sc_mine = 0.f;
        #pragma unroll
        for (int i = 0; i < 8; i++) {
            long long e = base + 2 * i + half;
            if (e >= E) e = E - 1;
            const float* ep = (e < E1) ? (emb1 + e * 64) : (emb2 + (e - E1) * 64);
            em[i] = __ldg((const float4*)ep + sub);
            float p = em[i].x * c4.x + em[i].y * c4.y + em[i].z * c4.z + em[i].w * c4.w;
            p += __shfl_xor_sync(0xffffffffu, p, 1);
            p += __shfl_xor_sync(0xffffffffu, p, 2);
            p += __shfl_xor_sync(0xffffffffu, p, 4);
            p += __shfl_xor_sync(0xffffffffu, p, 8);
            float s0 = __shfl_sync(0xffffffffu, p, 0);
            float s1 = __shfl_sync(0xffffffffu, p, 16);
            if (lane == 2 * i)     sc_mine = s0;
            if (lane == 2 * i + 1) sc_mine = s1;
        }

        // ee + fused CSR scatter on lanes 0..15
        float ee = 0.f;
        if (lane < 16 && ge < E) {
            float sc = sc_mine + ssd;
            float pw = sc > 0.f ? sc : GAT_ALPHA * sc;
            ee = __expf(-pw);
            int pos = atomicAdd(&g_cur[s], 1);
            g_adj[pos] = ((long long)(unsigned int)__float_as_uint(ee) << 32)
                       | (unsigned int)d;
        }

        // scatter w: phase i covers edges 2i (half 0) and 2i+1 (half 1)
        #pragma unroll
        for (int i = 0; i < 8; i++) {
            int j = 2 * i + half;
            float eej = __shfl_sync(0xffffffffu, ee, j);
            int   sij = __shfl_sync(0xffffffffu, s, j);
            float w0 = eej * em[i].x, w1 = eej * em[i].y;
            float w2 = eej * em[i].z, w3 = eej * em[i].w;
            float* wp = g_w + (size_t)sij * 64 + sub * 4;
            asm volatile("red.global.add.v4.f32 [%0], {%1, %2, %3, %4};"
                         :: "l"(wp), "f"(w0), "f"(w1), "f"(w2), "f"(w3) : "memory");
        }
    }
}

// ---------------------------------------------------------------------------
__global__ void transpose_a_kernel(const float* __restrict__ a) {
    int idx = blockIdx.x * 256 + threadIdx.x;
    if (idx < 320 * 128) {
        int k = idx >> 7, o = idx & 127;
        g_aT[idx] = a[o * 320 + k];
    }
}

// ---------------------------------------------------------------------------
// Node kernel: warp per node. Gathers xd[dst] (L2-resident rows of g_xsd),
// batches of 16 edges (MLP=16), prefetched. ydot + rs in registers.
// ---------------------------------------------------------------------------
__global__ void __launch_bounds__(256) node_kernel(int N) {
    const int warp = threadIdx.x >> 5;
    const int lane = threadIdx.x & 31;
    const int n = blockIdx.x * 8 + warp;
    if (n >= N) return;

    const int off0 = g_off[n];
    const int deg  = g_off[n + 1] - off0;

    float4 acc = make_float4(0.f, 0.f, 0.f, 0.f);
    float rs = 0.f;

    long long pk = (lane < 16 && lane < deg) ? g_adj[off0 + lane] : 0;

    for (int b = 0; b < deg; b += 16) {
        long long pk_next = (lane < 16 && b + 16 + lane < deg)
                          ? g_adj[off0 + b + 16 + lane] : 0;

        float eev[16];
        float4 xv[16];
        #pragma unroll
        for (int i = 0; i < 16; i++) {
            long long p = __shfl_sync(0xffffffffu, pk, i);
            int dd = (int)(p & 0xffffffffLL);
            eev[i] = __uint_as_float((unsigned int)((unsigned long long)p >> 32));
            xv[i] = __ldg((const float4*)(g_xsd + (size_t)dd * 256 + 128) + lane);
        }
        #pragma unroll
        for (int i = 0; i < 16; i++) {
            acc.x += eev[i] * xv[i].x;
            acc.y += eev[i] * xv[i].y;
            acc.z += eev[i] * xv[i].z;
            acc.w += eev[i] * xv[i].w;
            rs += eev[i];
        }
        pk = pk_next;
    }

    *(float4*)(g_ydot + (size_t)n * 128 + lane * 4) = acc;
    if (lane == 0) g_rowsum[n] = rs;
}

// ---------------------------------------------------------------------------
// Final: 128n x 128o per block, 256 threads, thread tile 8n x 8o, K=64 only
// (w @ a_rel^T), then out = elu( xs + inv*(ydot + wrel) ).
// ---------------------------------------------------------------------------
__global__ void __launch_bounds__(256, 2) final_kernel(float* __restrict__ out, int N)
{
    __shared__ float2 z_sm[128 * 33];     // [n][k] duplicated pairs, pitch 33
    __shared__ float  a_sm[32 * 132];     // [k][o], pitch 132
    __shared__ float  inv_sm[128];

    const int tid = threadIdx.x;
    const int warp = tid >> 5, lane = tid & 31;
    const int n0 = blockIdx.x * 128;

    const int nb = (warp >> 1) * 32 + (lane >> 3) * 8;  // 8 nodes
    const int ob = (warp & 1) * 64 + (lane & 7) * 8;    // 8 outs

    if (tid < 128) {
        float rs = (n0 + tid < N) ? g_rowsum[n0 + tid] : 0.f;
        inv_sm[tid] = rs > 0.f ? 1.f / rs : 0.f;
    }

    unsigned long long acc[8][4];
    #pragma unroll
    for (int j = 0; j < 8; j++)
        #pragma unroll
        for (int p = 0; p < 4; p++) acc[j][p] = 0ull;

    #pragma unroll 1
    for (int kc = 0; kc < 2; kc++) {
        __syncthreads();
        // stage a chunk: rows 256+kc*32 .. of aT (a_rel), 32k x 128o
        #pragma unroll
        for (int it = 0; it < 4; it++) {
            int i = tid + it * 256;
            int k = i >> 5, qq = i & 31;
            float4 av = *(const float4*)(g_aT + (size_t)(256 + kc * 32 + k) * 128 + qq * 4);
            *(float4*)&a_sm[k * 132 + qq * 4] = av;
        }
        // stage z chunk: w[n][kc*32 .. +32], duplicated
        #pragma unroll
        for (int it = 0; it < 4; it++) {
            int i = tid + it * 256;
            int n = i >> 3, kq = i & 7;
            float4 v = make_float4(0.f, 0.f, 0.f, 0.f);
            if (n0 + n < N)
                v = *(const float4*)(g_w + (size_t)(n0 + n) * 64 + kc * 32 + kq * 4);
            float2* zp = &z_sm[n * 33 + kq * 4];
            zp[0] = make_float2(v.x, v.x);
            zp[1] = make_float2(v.y, v.y);
            zp[2] = make_float2(v.z, v.z);
            zp[3] = make_float2(v.w, v.w);
        }
        __syncthreads();

        #pragma unroll 16
        for (int k = 0; k < 32; k++) {
            ulonglong2 A01 = *(const ulonglong2*)&a_sm[k * 132 + ob];
            ulonglong2 A23 = *(const ulonglong2*)&a_sm[k * 132 + ob + 4];
            #pragma unroll
            for (int j = 0; j < 8; j++) {
                unsigned long long zd = *(const unsigned long long*)&z_sm[(nb + j) * 33 + k];
                fma2(acc[j][0], zd, A01.x);
                fma2(acc[j][1], zd, A01.y);
                fma2(acc[j][2], zd, A23.x);
                fma2(acc[j][3], zd, A23.y);
            }
        }
    }

    // epilogue: out = elu( xs + inv*(ydot + wrel) )
    #pragma unroll
    for (int j = 0; j < 8; j++) {
        int n = n0 + nb + j;
        if (n < N) {
            float iv = inv_sm[nb + j];
            bool ok = iv > 0.f;
            float4 xsA = *(const float4*)(g_xsd + (size_t)n * 256 + ob);
            float4 xsB = *(const float4*)(g_xsd + (size_t)n * 256 + ob + 4);
            float4 ydA = *(const float4*)(g_ydot + (size_t)n * 128 + ob);
            float4 ydB = *(const float4*)(g_ydot + (size_t)n * 128 + ob + 4);
            float o[8];
            #pragma unroll
            for (int p = 0; p < 4; p++) {
                float2 f = unpack2(acc[j][p]);
                o[2 * p] = f.x; o[2 * p + 1] = f.y;
            }
            float xs[8] = {xsA.x, xsA.y, xsA.z, xsA.w, xsB.x, xsB.y, xsB.z, xsB.w};
            float yd[8] = {ydA.x, ydA.y, ydA.z, ydA.w, ydB.x, ydB.y, ydB.z, ydB.w};
            #pragma unroll
            for (int q = 0; q < 8; q++) {
                float v = xs[q] + iv * (yd[q] + o[q]);
                o[q] = ok ? (v > 0.f ? v : expm1f(v)) : 0.f;
            }
            float* dp = out + (size_t)n * 128 + ob;
            *(float4*)dp = make_float4(o[0], o[1], o[2], o[3]);
            *(float4*)(dp + 4) = make_float4(o[4], o[5], o[6], o[7]);
        }
    }
}

// ---------------------------------------------------------------------------
extern "C" void kernel_launch(void* const* d_in, const int* in_sizes, int n_in,
                              void* d_out, int out_size) {
    const float* x     = (const float*)d_in[0];
    const int*   edge1 = (const int*)  d_in[1];
    const float* emb1  = (const float*)d_in[2];
    const int*   edge2 = (const int*)  d_in[3];
    const float* emb2  = (const float*)d_in[4];
    const float* a     = (const float*)d_in[5];
    const float* a2    = (const float*)d_in[6];
    float* out = (float*)d_out;

    int N  = in_sizes[0] / 128;
    int E1 = in_sizes[1] / 2;
    int E2 = in_sizes[3] / 2;

    // launch #4 (the one ncu captures) = prep_kernel
    vec_kernel<<<1, 320>>>(a, a2);
    zero_kernel<<<1024, 256>>>(N);
    hist_kernel<<<1024, 256>>>(edge1, edge2, E1, E2);
    prep_kernel<<<(N + 15) / 16, 256>>>(x, a, N);
    scan_kernel<<<1, 1024>>>(N);
    transpose_a_kernel<<<160, 256>>>(a);
    passA_kernel<<<592, 256>>>(edge1, emb1, edge2, emb2, E1, E2);
    node_kernel<<<(N + 7) / 8, 256>>>(N);
    final_kernel<<<(N + 127) / 128, 256>>>(out, N);
}

// round 16
// speedup vs baseline: 1.1749x; 1.1749x over previous
#include <cuda_runtime.h>
#include <cstdint>

// ---------------------------------------------------------------------------
// SpGraphAttentionLayer (GAT forward).  N=50000, D=128, O=128, R=64, E=1e6.
//
// Factored form:
//   u = a2 @ a (320); c = u[256:320]
//   xs = x @ a_src^T ; xd = x @ a_dst^T            (prep, tiled GEMM)
//   sdot_s[n] = x[n]·u[0:128] ; sdot_d[n] = x[n]·u[128:256]  (folded in prep)
//   score[e]  = emb[e]·c + sdot_s[src] + sdot_d[dst]
//   ee[e]     = exp(-leaky(score))
//   rs[n] = Σ ee ; w[n] = Σ ee·emb[e] ; ydot[n] = Σ ee·xd[dst]
//   out[n] = rs>0 ? elu( xs[n] + (ydot[n] + w[n]@a_rel^T)/rs ) : 0
// ---------------------------------------------------------------------------

#define NMAX 50000
#define EMAX 1100000
#define GAT_ALPHA 0.2f

__device__ float g_xsd[(size_t)NMAX * 256];   // [n][0:128]=xs, [n][128:256]=xd
__device__ float g_sdot[(size_t)NMAX * 2];
__device__ float g_u[320];
__device__ float g_rowsum[NMAX];
__device__ float g_w[(size_t)NMAX * 64];
__device__ float g_ydot[(size_t)NMAX * 128];
__device__ float g_aT[320 * 128];             // a transposed: [k][o]
__device__ int       g_cnt[NMAX];
__device__ int       g_off[NMAX + 1];
__device__ int       g_cur[NMAX];
__device__ long long g_adj[EMAX];             // (bits(ee)<<32) | dst

__device__ __forceinline__ void fma2(unsigned long long &acc,
                                     unsigned long long a, unsigned long long b) {
    asm("fma.rn.f32x2 %0, %1, %2, %0;" : "+l"(acc) : "l"(a), "l"(b));
}
__device__ __forceinline__ float2 unpack2(unsigned long long v) {
    float2 r;
    asm("mov.b64 {%0, %1}, %2;" : "=f"(r.x), "=f"(r.y) : "l"(v));
    return r;
}

// ---------------------------------------------------------------------------
__global__ void vec_kernel(const float* __restrict__ a, const float* __restrict__ a2) {
    __shared__ float a2s[128];
    int t = threadIdx.x;
    if (t < 128) a2s[t] = a2[t];
    __syncthreads();
    if (t < 320) {
        float acc = 0.f;
        #pragma unroll 8
        for (int o = 0; o < 128; o++) acc += a2s[o] * a[o * 320 + t];
        g_u[t] = acc;
    }
}

// ---------------------------------------------------------------------------
__global__ void zero_kernel(int N) {
    int stride = gridDim.x * blockDim.x;
    int i = blockIdx.x * blockDim.x + threadIdx.x;
    int nw = N * 16;
    float4 z = make_float4(0.f, 0.f, 0.f, 0.f);
    for (int j = i; j < nw; j += stride) ((float4*)g_w)[j] = z;
    for (int j = i; j < N; j += stride) g_cnt[j] = 0;
}

__global__ void hist_kernel(const int* __restrict__ e1, const int* __restrict__ e2,
                            int E1, int E2) {
    int E = E1 + E2;
    int stride = gridDim.x * blockDim.x;
    for (int e = blockIdx.x * blockDim.x + threadIdx.x; e < E; e += stride) {
        int s = (e < E1) ? e1[e] : e2[e - E1];
        atomicAdd(&g_cnt[s], 1);
    }
}

__global__ void transpose_a_kernel(const float* __restrict__ a) {
    int idx = blockIdx.x * 256 + threadIdx.x;
    if (idx < 320 * 128) {
        int k = idx >> 7, o = idx & 127;
        g_aT[idx] = a[o * 320 + k];
    }
}

// ---------------------------------------------------------------------------
// prep: tiled GEMM. Block = 128 nodes x 128 outs; variant 0 -> xs (aT rows
// 0..127), variant 1 -> xd (aT rows 128..255). K=128 in 4 chunks of 32.
// Thread tile 8n x 8o (f32x2). sdot_s / sdot_d folded (x tile is in smem).
// ---------------------------------------------------------------------------
__global__ void __launch_bounds__(256, 2) prep_kernel(const float* __restrict__ x, int N)
{
    __shared__ float2 z_sm[128 * 33];     // [n][k] duplicated pairs
    __shared__ float  a_sm[32 * 132];     // [k][o]
    __shared__ float  us_sm[128];

    const int tid = threadIdx.x;
    const int warp = tid >> 5, lane = tid & 31;
    const int gx = blockIdx.x;
    const int variant = gx & 1;           // 0 = xs, 1 = xd
    const int n0 = (gx >> 1) * 128;

    const int nb = (warp >> 1) * 32 + (lane >> 3) * 8;  // 8 nodes
    const int ob = (warp & 1) * 64 + (lane & 7) * 8;    // 8 outs

    if (tid < 128) us_sm[tid] = g_u[variant * 128 + tid];

    unsigned long long acc[8][4];
    #pragma unroll
    for (int j = 0; j < 8; j++)
        #pragma unroll
        for (int p = 0; p < 4; p++) acc[j][p] = 0ull;

    float sdp = 0.f;                      // sdot partial: node tid>>1, half tid&1
    const int sn = tid >> 1, skh = (tid & 1) * 16;

    #pragma unroll 1
    for (int kc = 0; kc < 4; kc++) {
        __syncthreads();
        // stage a chunk: 32k x 128o from g_aT rows variant*128 + kc*32 ..
        #pragma unroll
        for (int it = 0; it < 4; it++) {
            int i = tid + it * 256;
            int k = i >> 5, qq = i & 31;
            float4 av = *(const float4*)(g_aT
                        + (size_t)(variant * 128 + kc * 32 + k) * 128 + qq * 4);
            *(float4*)&a_sm[k * 132 + qq * 4] = av;
        }
        // stage z chunk: x[n][kc*32 .. +32], duplicated
        #pragma unroll
        for (int it = 0; it < 4; it++) {
            int i = tid + it * 256;
            int n = i >> 3, kq = i & 7;
            float4 v = make_float4(0.f, 0.f, 0.f, 0.f);
            if (n0 + n < N)
                v = *(const float4*)(x + (size_t)(n0 + n) * 128 + kc * 32 + kq * 4);
            float2* zp = &z_sm[n * 33 + kq * 4];
            zp[0] = make_float2(v.x, v.x);
            zp[1] = make_float2(v.y, v.y);
            zp[2] = make_float2(v.z, v.z);
            zp[3] = make_float2(v.w, v.w);
        }
        __syncthreads();

        // sdot partial for this chunk
        #pragma unroll
        for (int j = 0; j < 16; j++) {
            int k = skh + j;
            sdp += z_sm[sn * 33 + k].x * us_sm[kc * 32 + k];
        }

        #pragma unroll 16
        for (int k = 0; k < 32; k++) {
            ulonglong2 A01 = *(const ulonglong2*)&a_sm[k * 132 + ob];
            ulonglong2 A23 = *(const ulonglong2*)&a_sm[k * 132 + ob + 4];
            #pragma unroll
            for (int j = 0; j < 8; j++) {
                unsigned long long zd = *(const unsigned long long*)&z_sm[(nb + j) * 33 + k];
                fma2(acc[j][0], zd, A01.x);
                fma2(acc[j][1], zd, A01.y);
                fma2(acc[j][2], zd, A23.x);
                fma2(acc[j][3], zd, A23.y);
            }
        }
    }

    // sdot: combine the two 16-k halves (adjacent threads) and store
    sdp += __shfl_xor_sync(0xffffffffu, sdp, 1);
    if ((tid & 1) == 0 && n0 + sn < N)
        g_sdot[2 * (n0 + sn) + variant] = sdp;

    // epilogue: write xs/xd
    #pragma unroll
    for (int j = 0; j < 8; j++) {
        int n = n0 + nb + j;
        if (n < N) {
            float o[8];
            #pragma unroll
            for (int p = 0; p < 4; p++) {
                float2 f = unpack2(acc[j][p]);
                o[2 * p] = f.x; o[2 * p + 1] = f.y;
            }
            float* dp = g_xsd + (size_t)n * 256 + variant * 128 + ob;
            *(float4*)dp = make_float4(o[0], o[1], o[2], o[3]);
            *(float4*)(dp + 4) = make_float4(o[4], o[5], o[6], o[7]);
        }
    }
}

// ---------------------------------------------------------------------------
__global__ void __launch_bounds__(1024) scan_kernel(int N) {
    __shared__ int sums[1024];
    int t = threadIdx.x;
    int CH = (N + 1023) >> 10;
    int lo = t * CH;
    int hi = lo + CH; if (hi > N) hi = N; if (lo > N) lo = N;

    int s = 0;
    for (int i = lo; i < hi; i++) s += g_cnt[i];
    sums[t] = s;
    __syncthreads();

    for (int off = 1; off < 1024; off <<= 1) {
        int v = (t >= off) ? sums[t - off] : 0;
        __syncthreads();
        sums[t] += v;
        __syncthreads();
    }

    int run = (t > 0) ? sums[t - 1] : 0;
    for (int i = lo; i < hi; i++) {
        int c = g_cnt[i];
        g_off[i] = run;
        g_cur[i] = run;
        run += c;
    }
    if (t == 1023) g_off[N] = run;
}

// ---------------------------------------------------------------------------
// passA: stream emb once. Outputs: w[src] += ee*emb (red.v4, register-resident
// emb), fused CSR scatter of (ee,dst).
// ---------------------------------------------------------------------------
__global__ void __launch_bounds__(256) passA_kernel(
    const int* __restrict__ edge1, const float* __restrict__ emb1,
    const int* __restrict__ edge2, const float* __restrict__ emb2,
    int E1i, int E2i)
{
    const long long E1 = E1i, E2 = E2i;
    const long long E = E1 + E2;
    const long long CH = (E + 15) >> 4;

    const int lane = threadIdx.x & 31;
    const int sub  = lane & 15;
    const int half = lane >> 4;

    long long gwarp = (long long)blockIdx.x * (blockDim.x >> 5) + (threadIdx.x >> 5);
    const long long nwarps = (long long)gridDim.x * (blockDim.x >> 5);

    const float4 c4 = *(const float4*)(g_u + 256 + sub * 4);

    for (long long ch = gwarp; ch < CH; ch += nwarps) {
        const long long base = ch << 4;

        long long ge = base + sub;
        long long gec = (ge < E) ? ge : (E - 1);
        int s, d;
        if (gec < E1) { s = edge1[gec]; d = edge1[E1 + gec]; }
        else { long long g2 = gec - E1; s = edge2[g2]; d = edge2[E2 + g2]; }
        float ssd = g_sdot[2 * s] + g_sdot[2 * d + 1];

        float4 em[8];
        float sc_mine = 0.f;
        #pragma unroll
        for (int i = 0; i < 8; i++) {
            long long e = base + 2 * i + half;
            if (e >= E) e = E - 1;
            const float* ep = (e < E1) ? (emb1 + e * 64) : (emb2 + (e - E1) * 64);
            em[i] = __ldg((const float4*)ep + sub);
            float p = em[i].x * c4.x + em[i].y * c4.y + em[i].z * c4.z + em[i].w * c4.w;
            p += __shfl_xor_sync(0xffffffffu, p, 1);
            p += __shfl_xor_sync(0xffffffffu, p, 2);
            p += __shfl_xor_sync(0xffffffffu, p, 4);
            p += __shfl_xor_sync(0xffffffffu, p, 8);
            float s0 = __shfl_sync(0xffffffffu, p, 0);
            float s1 = __shfl_sync(0xffffffffu, p, 16);
            if (lane == 2 * i)     sc_mine = s0;
            if (lane == 2 * i + 1) sc_mine = s1;
        }

        float ee = 0.f;
        if (lane < 16 && ge < E) {
            float sc = sc_mine + ssd;
            float pw = sc > 0.f ? sc : GAT_ALPHA * sc;
            ee = __expf(-pw);
            int pos = atomicAdd(&g_cur[s], 1);
            g_adj[pos] = ((long long)(unsigned int)__float_as_uint(ee) << 32)
                       | (unsigned int)d;
        }

        #pragma unroll
        for (int i = 0; i < 8; i++) {
            int j = 2 * i + half;
            float eej = __shfl_sync(0xffffffffu, ee, j);
            int   sij = __shfl_sync(0xffffffffu, s, j);
            float w0 = eej * em[i].x, w1 = eej * em[i].y;
            float w2 = eej * em[i].z, w3 = eej * em[i].w;
            float* wp = g_w + (size_t)sij * 64 + sub * 4;
            asm volatile("red.global.add.v4.f32 [%0], {%1, %2, %3, %4};"
                         :: "l"(wp), "f"(w0), "f"(w1), "f"(w2), "f"(w3) : "memory");
        }
    }
}

// ---------------------------------------------------------------------------
// Node kernel: warp per node. Gathers xd[dst] (L2-resident rows of g_xsd),
// batches of 16 edges (MLP=16), prefetched. ydot + rs in registers.
// ---------------------------------------------------------------------------
__global__ void __launch_bounds__(256) node_kernel(int N) {
    const int warp = threadIdx.x >> 5;
    const int lane = threadIdx.x & 31;
    const int n = blockIdx.x * 8 + warp;
    if (n >= N) return;

    const int off0 = g_off[n];
    const int deg  = g_off[n + 1] - off0;

    float4 acc = make_float4(0.f, 0.f, 0.f, 0.f);
    float rs = 0.f;

    long long pk = (lane < 16 && lane < deg) ? g_adj[off0 + lane] : 0;

    for (int b = 0; b < deg; b += 16) {
        long long pk_next = (lane < 16 && b + 16 + lane < deg)
                          ? g_adj[off0 + b + 16 + lane] : 0;

        float eev[16];
        float4 xv[16];
        #pragma unroll
        for (int i = 0; i < 16; i++) {
            long long p = __shfl_sync(0xffffffffu, pk, i);
            int dd = (int)(p & 0xffffffffLL);
            eev[i] = __uint_as_float((unsigned int)((unsigned long long)p >> 32));
            xv[i] = __ldg((const float4*)(g_xsd + (size_t)dd * 256 + 128) + lane);
        }
        #pragma unroll
        for (int i = 0; i < 16; i++) {
            acc.x += eev[i] * xv[i].x;
            acc.y += eev[i] * xv[i].y;
            acc.z += eev[i] * xv[i].z;
            acc.w += eev[i] * xv[i].w;
            rs += eev[i];
        }
        pk = pk_next;
    }

    *(float4*)(g_ydot + (size_t)n * 128 + lane * 4) = acc;
    if (lane == 0) g_rowsum[n] = rs;
}

// ---------------------------------------------------------------------------
// Final: 128n x 128o per block, thread tile 8n x 8o, K=64 (w @ a_rel^T),
// then out = elu( xs + inv*(ydot + wrel) ).
// ---------------------------------------------------------------------------
__global__ void __launch_bounds__(256, 2) final_kernel(float* __restrict__ out, int N)
{
    __shared__ float2 z_sm[128 * 33];
    __shared__ float  a_sm[32 * 132];
    __shared__ float  inv_sm[128];

    const int tid = threadIdx.x;
    const int warp = tid >> 5, lane = tid & 31;
    const int n0 = blockIdx.x * 128;

    const int nb = (warp >> 1) * 32 + (lane >> 3) * 8;
    const int ob = (warp & 1) * 64 + (lane & 7) * 8;

    if (tid < 128) {
        float rs = (n0 + tid < N) ? g_rowsum[n0 + tid] : 0.f;
        inv_sm[tid] = rs > 0.f ? 1.f / rs : 0.f;
    }

    unsigned long long acc[8][4];
    #pragma unroll
    for (int j = 0; j < 8; j++)
        #pragma unroll
        for (int p = 0; p < 4; p++) acc[j][p] = 0ull;

    #pragma unroll 1
    for (int kc = 0; kc < 2; kc++) {
        __syncthreads();
        #pragma unroll
        for (int it = 0; it < 4; it++) {
            int i = tid + it * 256;
            int k = i >> 5, qq = i & 31;
            float4 av = *(const float4*)(g_aT + (size_t)(256 + kc * 32 + k) * 128 + qq * 4);
            *(float4*)&a_sm[k * 132 + qq * 4] = av;
        }
        #pragma unroll
        for (int it = 0; it < 4; it++) {
            int i = tid + it * 256;
            int n = i >> 3, kq = i & 7;
            float4 v = make_float4(0.f, 0.f, 0.f, 0.f);
            if (n0 + n < N)
                v = *(const float4*)(g_w + (size_t)(n0 + n) * 64 + kc * 32 + kq * 4);
            float2* zp = &z_sm[n * 33 + kq * 4];
            zp[0] = make_float2(v.x, v.x);
            zp[1] = make_float2(v.y, v.y);
            zp[2] = make_float2(v.z, v.z);
            zp[3] = make_float2(v.w, v.w);
        }
        __syncthreads();

        #pragma unroll 16
        for (int k = 0; k < 32; k++) {
            ulonglong2 A01 = *(const ulonglong2*)&a_sm[k * 132 + ob];
            ulonglong2 A23 = *(const ulonglong2*)&a_sm[k * 132 + ob + 4];
            #pragma unroll
            for (int j = 0; j < 8; j++) {
                unsigned long long zd = *(const unsigned long long*)&z_sm[(nb + j) * 33 + k];
                fma2(acc[j][0], zd, A01.x);
                fma2(acc[j][1], zd, A01.y);
                fma2(acc[j][2], zd, A23.x);
                fma2(acc[j][3], zd, A23.y);
            }
        }
    }

    #pragma unroll
    for (int j = 0; j < 8; j++) {
        int n = n0 + nb + j;
        if (n < N) {
            float iv = inv_sm[nb + j];
            bool ok = iv > 0.f;
            float4 xsA = *(const float4*)(g_xsd + (size_t)n * 256 + ob);
            float4 xsB = *(const float4*)(g_xsd + (size_t)n * 256 + ob + 4);
            float4 ydA = *(const float4*)(g_ydot + (size_t)n * 128 + ob);
            float4 ydB = *(const float4*)(g_ydot + (size_t)n * 128 + ob + 4);
            float o[8];
            #pragma unroll
            for (int p = 0; p < 4; p++) {
                float2 f = unpack2(acc[j][p]);
                o[2 * p] = f.x; o[2 * p + 1] = f.y;
            }
            float xs[8] = {xsA.x, xsA.y, xsA.z, xsA.w, xsB.x, xsB.y, xsB.z, xsB.w};
            float yd[8] = {ydA.x, ydA.y, ydA.z, ydA.w, ydB.x, ydB.y, ydB.z, ydB.w};
            #pragma unroll
            for (int q = 0; q < 8; q++) {
                float v = xs[q] + iv * (yd[q] + o[q]);
                o[q] = ok ? (v > 0.f ? v : expm1f(v)) : 0.f;
            }
            float* dp = out + (size_t)n * 128 + ob;
            *(float4*)dp = make_float4(o[0], o[1], o[2], o[3]);
            *(float4*)(dp + 4) = make_float4(o[4], o[5], o[6], o[7]);
        }
    }
}

// ---------------------------------------------------------------------------
extern "C" void kernel_launch(void* const* d_in, const int* in_sizes, int n_in,
                              void* d_out, int out_size) {
    const float* x     = (const float*)d_in[0];
    const int*   edge1 = (const int*)  d_in[1];
    const float* emb1  = (const float*)d_in[2];
    const int*   edge2 = (const int*)  d_in[3];
    const float* emb2  = (const float*)d_in[4];
    const float* a     = (const float*)d_in[5];
    const float* a2    = (const float*)d_in[6];
    float* out = (float*)d_out;

    int N  = in_sizes[0] / 128;
    int E1 = in_sizes[1] / 2;
    int E2 = in_sizes[3] / 2;

    // launch #4 (the one ncu captures) = prep_kernel (tiled GEMM)
    vec_kernel<<<1, 320>>>(a, a2);
    zero_kernel<<<1024, 256>>>(N);
    transpose_a_kernel<<<160, 256>>>(a);
    prep_kernel<<<((N + 127) / 128) * 2, 256>>>(x, N);
    hist_kernel<<<1024, 256>>>(edge1, edge2, E1, E2);
    scan_kernel<<<1, 1024>>>(N);
    passA_kernel<<<592, 256>>>(edge1, emb1, edge2, emb2, E1, E2);
    node_kernel<<<(N + 7) / 8, 256>>>(N);
    final_kernel<<<(N + 127) / 128, 256>>>(out, N);
}

// round 17
// speedup vs baseline: 1.3053x; 1.1110x over previous
#include <cuda_runtime.h>
#include <cstdint>

// ---------------------------------------------------------------------------
// SpGraphAttentionLayer (GAT forward).  N=50000, D=128, O=128, R=64, E=1e6.
//
// Factored form:
//   u = a2 @ a (320); c = u[256:320]
//   xs = x @ a_src^T ; xd = x @ a_dst^T            (prep, tiled GEMM)
//   sdot_s[n] = x[n]·u[0:128] ; sdot_d[n] = x[n]·u[128:256]  (folded in prep)
//   score[e]  = emb[e]·c + sdot_s[src] + sdot_d[dst]
//   ee[e]     = exp(-leaky(score))
//   rs[n] = Σ ee ; w[n] = Σ ee·emb[e] ; ydot[n] = Σ ee·xd[dst]
//   out[n] = rs>0 ? elu( xs[n] + (ydot[n] + w[n]@a_rel^T)/rs ) : 0
// ---------------------------------------------------------------------------

#define NMAX 50000
#define EMAX 1100000
#define GAT_ALPHA 0.2f

__device__ float g_xsd[(size_t)NMAX * 256];   // [n][0:128]=xs, [n][128:256]=xd
__device__ float g_sdot[(size_t)NMAX * 2];
__device__ float g_u[320];
__device__ float g_rowsum[NMAX];
__device__ float g_w[(size_t)NMAX * 64];
__device__ float g_ydot[(size_t)NMAX * 128];
__device__ float g_aT[320 * 128];             // a transposed: [k][o]
__device__ int       g_cnt[NMAX];
__device__ int       g_off[NMAX + 1];
__device__ int       g_cur[NMAX];
__device__ long long g_adj[EMAX];             // (bits(ee)<<32) | dst

__device__ __forceinline__ void fma2(unsigned long long &acc,
                                     unsigned long long a, unsigned long long b) {
    asm("fma.rn.f32x2 %0, %1, %2, %0;" : "+l"(acc) : "l"(a), "l"(b));
}
__device__ __forceinline__ float2 unpack2(unsigned long long v) {
    float2 r;
    asm("mov.b64 {%0, %1}, %2;" : "=f"(r.x), "=f"(r.y) : "l"(v));
    return r;
}

// ---------------------------------------------------------------------------
__global__ void vec_kernel(const float* __restrict__ a, const float* __restrict__ a2) {
    __shared__ float a2s[128];
    int t = threadIdx.x;
    if (t < 128) a2s[t] = a2[t];
    __syncthreads();
    if (t < 320) {
        float acc = 0.f;
        #pragma unroll 8
        for (int o = 0; o < 128; o++) acc += a2s[o] * a[o * 320 + t];
        g_u[t] = acc;
    }
}

// ---------------------------------------------------------------------------
__global__ void zero_kernel(int N) {
    int stride = gridDim.x * blockDim.x;
    int i = blockIdx.x * blockDim.x + threadIdx.x;
    int nw = N * 16;
    float4 z = make_float4(0.f, 0.f, 0.f, 0.f);
    for (int j = i; j < nw; j += stride) ((float4*)g_w)[j] = z;
    for (int j = i; j < N; j += stride) g_cnt[j] = 0;
}

__global__ void hist_kernel(const int* __restrict__ e1, const int* __restrict__ e2,
                            int E1, int E2) {
    int E = E1 + E2;
    int stride = gridDim.x * blockDim.x;
    for (int e = blockIdx.x * blockDim.x + threadIdx.x; e < E; e += stride) {
        int s = (e < E1) ? e1[e] : e2[e - E1];
        atomicAdd(&g_cnt[s], 1);
    }
}

__global__ void transpose_a_kernel(const float* __restrict__ a) {
    int idx = blockIdx.x * 256 + threadIdx.x;
    if (idx < 320 * 128) {
        int k = idx >> 7, o = idx & 127;
        g_aT[idx] = a[o * 320 + k];
    }
}

// ---------------------------------------------------------------------------
// prep: tiled GEMM. Block = 128 nodes x 128 outs; variant 0 -> xs, 1 -> xd.
// K=128 in 4 chunks of 32. Thread tile 8n x 8o (f32x2). sdot folded.
// ---------------------------------------------------------------------------
__global__ void __launch_bounds__(256, 2) prep_kernel(const float* __restrict__ x, int N)
{
    __shared__ float2 z_sm[128 * 33];
    __shared__ float  a_sm[32 * 132];
    __shared__ float  us_sm[128];

    const int tid = threadIdx.x;
    const int warp = tid >> 5, lane = tid & 31;
    const int gx = blockIdx.x;
    const int variant = gx & 1;
    const int n0 = (gx >> 1) * 128;

    const int nb = (warp >> 1) * 32 + (lane >> 3) * 8;
    const int ob = (warp & 1) * 64 + (lane & 7) * 8;

    if (tid < 128) us_sm[tid] = g_u[variant * 128 + tid];

    unsigned long long acc[8][4];
    #pragma unroll
    for (int j = 0; j < 8; j++)
        #pragma unroll
        for (int p = 0; p < 4; p++) acc[j][p] = 0ull;

    float sdp = 0.f;
    const int sn = tid >> 1, skh = (tid & 1) * 16;

    #pragma unroll 1
    for (int kc = 0; kc < 4; kc++) {
        __syncthreads();
        #pragma unroll
        for (int it = 0; it < 4; it++) {
            int i = tid + it * 256;
            int k = i >> 5, qq = i & 31;
            float4 av = *(const float4*)(g_aT
                        + (size_t)(variant * 128 + kc * 32 + k) * 128 + qq * 4);
            *(float4*)&a_sm[k * 132 + qq * 4] = av;
        }
        #pragma unroll
        for (int it = 0; it < 4; it++) {
            int i = tid + it * 256;
            int n = i >> 3, kq = i & 7;
            float4 v = make_float4(0.f, 0.f, 0.f, 0.f);
            if (n0 + n < N)
                v = *(const float4*)(x + (size_t)(n0 + n) * 128 + kc * 32 + kq * 4);
            float2* zp = &z_sm[n * 33 + kq * 4];
            zp[0] = make_float2(v.x, v.x);
            zp[1] = make_float2(v.y, v.y);
            zp[2] = make_float2(v.z, v.z);
            zp[3] = make_float2(v.w, v.w);
        }
        __syncthreads();

        #pragma unroll
        for (int j = 0; j < 16; j++) {
            int k = skh + j;
            sdp += z_sm[sn * 33 + k].x * us_sm[kc * 32 + k];
        }

        #pragma unroll 16
        for (int k = 0; k < 32; k++) {
            ulonglong2 A01 = *(const ulonglong2*)&a_sm[k * 132 + ob];
            ulonglong2 A23 = *(const ulonglong2*)&a_sm[k * 132 + ob + 4];
            #pragma unroll
            for (int j = 0; j < 8; j++) {
                unsigned long long zd = *(const unsigned long long*)&z_sm[(nb + j) * 33 + k];
                fma2(acc[j][0], zd, A01.x);
                fma2(acc[j][1], zd, A01.y);
                fma2(acc[j][2], zd, A23.x);
                fma2(acc[j][3], zd, A23.y);
            }
        }
    }

    sdp += __shfl_xor_sync(0xffffffffu, sdp, 1);
    if ((tid & 1) == 0 && n0 + sn < N)
        g_sdot[2 * (n0 + sn) + variant] = sdp;

    #pragma unroll
    for (int j = 0; j < 8; j++) {
        int n = n0 + nb + j;
        if (n < N) {
            float o[8];
            #pragma unroll
            for (int p = 0; p < 4; p++) {
                float2 f = unpack2(acc[j][p]);
                o[2 * p] = f.x; o[2 * p + 1] = f.y;
            }
            float* dp = g_xsd + (size_t)n * 256 + variant * 128 + ob;
            *(float4*)dp = make_float4(o[0], o[1], o[2], o[3]);
            *(float4*)(dp + 4) = make_float4(o[4], o[5], o[6], o[7]);
        }
    }
}

// ---------------------------------------------------------------------------
__global__ void __launch_bounds__(1024) scan_kernel(int N) {
    __shared__ int sums[1024];
    int t = threadIdx.x;
    int CH = (N + 1023) >> 10;
    int lo = t * CH;
    int hi = lo + CH; if (hi > N) hi = N; if (lo > N) lo = N;

    int s = 0;
    for (int i = lo; i < hi; i++) s += g_cnt[i];
    sums[t] = s;
    __syncthreads();

    for (int off = 1; off < 1024; off <<= 1) {
        int v = (t >= off) ? sums[t - off] : 0;
        __syncthreads();
        sums[t] += v;
        __syncthreads();
    }

    int run = (t > 0) ? sums[t - 1] : 0;
    for (int i = lo; i < hi; i++) {
        int c = g_cnt[i];
        g_off[i] = run;
        g_cur[i] = run;
        run += c;
    }
    if (t == 1023) g_off[N] = run;
}

// ---------------------------------------------------------------------------
// passA: stream emb once. w[src] += ee*emb (red.v4) + fused CSR scatter.
// 32 regs -> run 8 blocks/SM (grid 1184) for latency hiding.
// ---------------------------------------------------------------------------
__global__ void __launch_bounds__(256) passA_kernel(
    const int* __restrict__ edge1, const float* __restrict__ emb1,
    const int* __restrict__ edge2, const float* __restrict__ emb2,
    int E1i, int E2i)
{
    const long long E1 = E1i, E2 = E2i;
    const long long E = E1 + E2;
    const long long CH = (E + 15) >> 4;

    const int lane = threadIdx.x & 31;
    const int sub  = lane & 15;
    const int half = lane >> 4;

    long long gwarp = (long long)blockIdx.x * (blockDim.x >> 5) + (threadIdx.x >> 5);
    const long long nwarps = (long long)gridDim.x * (blockDim.x >> 5);

    const float4 c4 = *(const float4*)(g_u + 256 + sub * 4);

    for (long long ch = gwarp; ch < CH; ch += nwarps) {
        const long long base = ch << 4;

        long long ge = base + sub;
        long long gec = (ge < E) ? ge : (E - 1);
        int s, d;
        if (gec < E1) { s = edge1[gec]; d = edge1[E1 + gec]; }
        else { long long g2 = gec - E1; s = edge2[g2]; d = edge2[E2 + g2]; }
        float ssd = g_sdot[2 * s] + g_sdot[2 * d + 1];

        float4 em[8];
        float sc_mine = 0.f;
        #pragma unroll
        for (int i = 0; i < 8; i++) {
            long long e = base + 2 * i + half;
            if (e >= E) e = E - 1;
            const float* ep = (e < E1) ? (emb1 + e * 64) : (emb2 + (e - E1) * 64);
            em[i] = __ldg((const float4*)ep + sub);
            float p = em[i].x * c4.x + em[i].y * c4.y + em[i].z * c4.z + em[i].w * c4.w;
            p += __shfl_xor_sync(0xffffffffu, p, 1);
            p += __shfl_xor_sync(0xffffffffu, p, 2);
            p += __shfl_xor_sync(0xffffffffu, p, 4);
            p += __shfl_xor_sync(0xffffffffu, p, 8);
            float s0 = __shfl_sync(0xffffffffu, p, 0);
            float s1 = __shfl_sync(0xffffffffu, p, 16);
            if (lane == 2 * i)     sc_mine = s0;
            if (lane == 2 * i + 1) sc_mine = s1;
        }

        float ee = 0.f;
        if (lane < 16 && ge < E) {
            float sc = sc_mine + ssd;
            float pw = sc > 0.f ? sc : GAT_ALPHA * sc;
            ee = __expf(-pw);
            int pos = atomicAdd(&g_cur[s], 1);
            g_adj[pos] = ((long long)(unsigned int)__float_as_uint(ee) << 32)
                       | (unsigned int)d;
        }

        #pragma unroll
        for (int i = 0; i < 8; i++) {
            int j = 2 * i + half;
            float eej = __shfl_sync(0xffffffffu, ee, j);
            int   sij = __shfl_sync(0xffffffffu, s, j);
            float w0 = eej * em[i].x, w1 = eej * em[i].y;
            float w2 = eej * em[i].z, w3 = eej * em[i].w;
            float* wp = g_w + (size_t)sij * 64 + sub * 4;
            asm volatile("red.global.add.v4.f32 [%0], {%1, %2, %3, %4};"
                         :: "l"(wp), "f"(w0), "f"(w1), "f"(w2), "f"(w3) : "memory");
        }
    }
}

// ---------------------------------------------------------------------------
// Node kernel: warp per node, xd-row gather. Batches of 8 (MLP=8) with pk
// prefetch; __launch_bounds__(256,4) for >=4 blocks/SM (occupancy > MLP).
// ---------------------------------------------------------------------------
__global__ void __launch_bounds__(256, 4) node_kernel(int N) {
    const int warp = threadIdx.x >> 5;
    const int lane = threadIdx.x & 31;
    const int n = blockIdx.x * 8 + warp;
    if (n >= N) return;

    const int off0 = g_off[n];
    const int deg  = g_off[n + 1] - off0;

    float4 acc = make_float4(0.f, 0.f, 0.f, 0.f);
    float rs = 0.f;

    long long pk = (lane < 8 && lane < deg) ? g_adj[off0 + lane] : 0;

    for (int b = 0; b < deg; b += 8) {
        long long pk_next = (lane < 8 && b + 8 + lane < deg)
                          ? g_adj[off0 + b + 8 + lane] : 0;

        float eev[8];
        float4 xv[8];
        #pragma unroll
        for (int i = 0; i < 8; i++) {
            long long p = __shfl_sync(0xffffffffu, pk, i);
            int dd = (int)(p & 0xffffffffLL);
            eev[i] = __uint_as_float((unsigned int)((unsigned long long)p >> 32));
            xv[i] = __ldg((const float4*)(g_xsd + (size_t)dd * 256 + 128) + lane);
        }
        #pragma unroll
        for (int i = 0; i < 8; i++) {
            acc.x += eev[i] * xv[i].x;
            acc.y += eev[i] * xv[i].y;
            acc.z += eev[i] * xv[i].z;
            acc.w += eev[i] * xv[i].w;
            rs += eev[i];
        }
        pk = pk_next;
    }

    *(float4*)(g_ydot + (size_t)n * 128 + lane * 4) = acc;
    if (lane == 0) g_rowsum[n] = rs;
}

// ---------------------------------------------------------------------------
// Final: 128n x 128o per block, thread tile 8n x 8o, K=64 (w @ a_rel^T),
// then out = elu( xs + inv*(ydot + wrel) ).
// ---------------------------------------------------------------------------
__global__ void __launch_bounds__(256, 2) final_kernel(float* __restrict__ out, int N)
{
    __shared__ float2 z_sm[128 * 33];
    __shared__ float  a_sm[32 * 132];
    __shared__ float  inv_sm[128];

    const int tid = threadIdx.x;
    const int warp = tid >> 5, lane = tid & 31;
    const int n0 = blockIdx.x * 128;

    const int nb = (warp >> 1) * 32 + (lane >> 3) * 8;
    const int ob = (warp & 1) * 64 + (lane & 7) * 8;

    if (tid < 128) {
        float rs = (n0 + tid < N) ? g_rowsum[n0 + tid] : 0.f;
        inv_sm[tid] = rs > 0.f ? 1.f / rs : 0.f;
    }

    unsigned long long acc[8][4];
    #pragma unroll
    for (int j = 0; j < 8; j++)
        #pragma unroll
        for (int p = 0; p < 4; p++) acc[j][p] = 0ull;

    #pragma unroll 1
    for (int kc = 0; kc < 2; kc++) {
        __syncthreads();
        #pragma unroll
        for (int it = 0; it < 4; it++) {
            int i = tid + it * 256;
            int k = i >> 5, qq = i & 31;
            float4 av = *(const float4*)(g_aT + (size_t)(256 + kc * 32 + k) * 128 + qq * 4);
            *(float4*)&a_sm[k * 132 + qq * 4] = av;
        }
        #pragma unroll
        for (int it = 0; it < 4; it++) {
            int i = tid + it * 256;
            int n = i >> 3, kq = i & 7;
            float4 v = make_float4(0.f, 0.f, 0.f, 0.f);
            if (n0 + n < N)
                v = *(const float4*)(g_w + (size_t)(n0 + n) * 64 + kc * 32 + kq * 4);
            float2* zp = &z_sm[n * 33 + kq * 4];
            zp[0] = make_float2(v.x, v.x);
            zp[1] = make_float2(v.y, v.y);
            zp[2] = make_float2(v.z, v.z);
            zp[3] = make_float2(v.w, v.w);
        }
        __syncthreads();

        #pragma unroll 16
        for (int k = 0; k < 32; k++) {
            ulonglong2 A01 = *(const ulonglong2*)&a_sm[k * 132 + ob];
            ulonglong2 A23 = *(const ulonglong2*)&a_sm[k * 132 + ob + 4];
            #pragma unroll
            for (int j = 0; j < 8; j++) {
                unsigned long long zd = *(const unsigned long long*)&z_sm[(nb + j) * 33 + k];
                fma2(acc[j][0], zd, A01.x);
                fma2(acc[j][1], zd, A01.y);
                fma2(acc[j][2], zd, A23.x);
                fma2(acc[j][3], zd, A23.y);
            }
        }
    }

    #pragma unroll
    for (int j = 0; j < 8; j++) {
        int n = n0 + nb + j;
        if (n < N) {
            float iv = inv_sm[nb + j];
            bool ok = iv > 0.f;
            float4 xsA = *(const float4*)(g_xsd + (size_t)n * 256 + ob);
            float4 xsB = *(const float4*)(g_xsd + (size_t)n * 256 + ob + 4);
            float4 ydA = *(const float4*)(g_ydot + (size_t)n * 128 + ob);
            float4 ydB = *(const float4*)(g_ydot + (size_t)n * 128 + ob + 4);
            float o[8];
            #pragma unroll
            for (int p = 0; p < 4; p++) {
                float2 f = unpack2(acc[j][p]);
                o[2 * p] = f.x; o[2 * p + 1] = f.y;
            }
            float xs[8] = {xsA.x, xsA.y, xsA.z, xsA.w, xsB.x, xsB.y, xsB.z, xsB.w};
            float yd[8] = {ydA.x, ydA.y, ydA.z, ydA.w, ydB.x, ydB.y, ydB.z, ydB.w};
            #pragma unroll
            for (int q = 0; q < 8; q++) {
                float v = xs[q] + iv * (yd[q] + o[q]);
                o[q] = ok ? (v > 0.f ? v : expm1f(v)) : 0.f;
            }
            float* dp = out + (size_t)n * 128 + ob;
            *(float4*)dp = make_float4(o[0], o[1], o[2], o[3]);
            *(float4*)(dp + 4) = make_float4(o[4], o[5], o[6], o[7]);
        }
    }
}

// ---------------------------------------------------------------------------
extern "C" void kernel_launch(void* const* d_in, const int* in_sizes, int n_in,
                              void* d_out, int out_size) {
    const float* x     = (const float*)d_in[0];
    const int*   edge1 = (const int*)  d_in[1];
    const float* emb1  = (const float*)d_in[2];
    const int*   edge2 = (const int*)  d_in[3];
    const float* emb2  = (const float*)d_in[4];
    const float* a     = (const float*)d_in[5];
    const float* a2    = (const float*)d_in[6];
    float* out = (float*)d_out;

    int N  = in_sizes[0] / 128;
    int E1 = in_sizes[1] / 2;
    int E2 = in_sizes[3] / 2;

    // launch #4 (the one ncu captures) = prep_kernel
    vec_kernel<<<1, 320>>>(a, a2);
    zero_kernel<<<1024, 256>>>(N);
    transpose_a_kernel<<<160, 256>>>(a);
    prep_kernel<<<((N + 127) / 128) * 2, 256>>>(x, N);
    hist_kernel<<<1024, 256>>>(edge1, edge2, E1, E2);
    scan_kernel<<<1, 1024>>>(N);
    passA_kernel<<<1184, 256>>>(edge1, emb1, edge2, emb2, E1, E2);
    node_kernel<<<(N + 7) / 8, 256>>>(N);
    final_kernel<<<(N + 127) / 128, 256>>>(out, N);
}